// round 10
// baseline (speedup 1.0000x reference)
#include <cuda_runtime.h>
#include <cstddef>

// DynamicFilterLayer: out[n,c,h,w] = sum_{i,j} xpad[n,c,h+i,w+j] * filters[n,i*9+j,h,w] + bias[n,0,h,w]
// N=2, C=8, H=256, W=512, K=9, pad=4.
// R8: split each row into 2 half-rows along w (WPT 4->2), grid 1024. No tap duplication
// (taps are per-pixel; w-ranges disjoint). 2x warps -> occ ~40%. Loads front-batched
// (float2), all edge handling via uniform predicates at float2 granularity.

#define N_  2
#define C_  8
#define H_  256
#define W_  512
#define KK  9
#define PAD 4
#define WPT 2   // output columns per thread

__global__ void __launch_bounds__(128) dfl_kernel(
    const float* __restrict__ x,      // [N, C, H, W]
    const float* __restrict__ f,      // [N, 81, H, W]
    const float* __restrict__ b,      // [N, 1, H, W]
    float* __restrict__ out)          // [N, C, H, W]
{
    const int row  = blockIdx.x >> 1;                       // (n, h) row id
    const int half = blockIdx.x & 1;                        // which half of the row
    const int n    = row >> 8;                              // / H_
    const int h    = row & 255;                             // % H_
    const int w0   = half * (W_ / 2) + threadIdx.x * WPT;   // even, 0..510

    const size_t HW = (size_t)H_ * W_;

    // accumulators initialized with bias
    float acc[C_][WPT];
    {
        const float2 bv = *reinterpret_cast<const float2*>(b + (size_t)n * HW + (size_t)h * W_ + w0);
        #pragma unroll
        for (int c = 0; c < C_; c++) { acc[c][0] = bv.x; acc[c][1] = bv.y; }
    }

    const int i0 = (h < PAD) ? (PAD - h) : 0;
    const int i1 = (h > H_ - 1 - PAD) ? (PAD + H_ - h) : KK;

    const float* ftap = f + (size_t)n * (KK * KK) * HW + (size_t)h * W_ + w0 + (size_t)i0 * KK * HW;
    const float* xrow = x + (size_t)n * C_ * HW + (size_t)(h + i0 - PAD) * W_ + w0;

    // window covers x[w0-4 .. w0+5] as 5 float2s; uniform per-thread validity
    const bool v_lo2 = (w0 >= 4);          // x[w0-4], x[w0-3]
    const bool v_lo1 = (w0 >= 2);          // x[w0-2], x[w0-1]
    const bool v_hi1 = (w0 <= W_ - 4);     // x[w0+2], x[w0+3]
    const bool v_hi2 = (w0 <= W_ - 6);     // x[w0+4], x[w0+5]

    const float2 z2 = make_float2(0.f, 0.f);

    for (int i = i0; i < i1; i++) {
        // ---- batch 1: all 9 tap float2s ----
        float2 t[KK];
        #pragma unroll
        for (int j = 0; j < KK; j++)
            t[j] = *reinterpret_cast<const float2*>(ftap + (size_t)j * HW);

        // ---- batch 2: x windows for channels 0..3 (20 loads in flight) ----
        float2 a0[4], a1[4], a2[4], a3[4], a4[4];
        #pragma unroll
        for (int c = 0; c < 4; c++) {
            const float2* xr = reinterpret_cast<const float2*>(xrow + (size_t)c * HW);
            a0[c] = v_lo2 ? xr[-2] : z2;
            a1[c] = v_lo1 ? xr[-1] : z2;
            a2[c] = xr[0];
            a3[c] = v_hi1 ? xr[1] : z2;
            a4[c] = v_hi2 ? xr[2] : z2;
        }

        // ---- compute channels 0..3 ----
        #pragma unroll
        for (int c = 0; c < 4; c++) {
            const float xw[WPT + KK - 1] = {
                a0[c].x, a0[c].y, a1[c].x, a1[c].y, a2[c].x,
                a2[c].y, a3[c].x, a3[c].y, a4[c].x, a4[c].y };
            #pragma unroll
            for (int j = 0; j < KK; j++) {
                acc[c][0] = fmaf(xw[j + 0], t[j].x, acc[c][0]);
                acc[c][1] = fmaf(xw[j + 1], t[j].y, acc[c][1]);
            }
        }

        // ---- batch 3: x windows for channels 4..7 ----
        #pragma unroll
        for (int c = 0; c < 4; c++) {
            const float2* xr = reinterpret_cast<const float2*>(xrow + (size_t)(c + 4) * HW);
            a0[c] = v_lo2 ? xr[-2] : z2;
            a1[c] = v_lo1 ? xr[-1] : z2;
            a2[c] = xr[0];
            a3[c] = v_hi1 ? xr[1] : z2;
            a4[c] = v_hi2 ? xr[2] : z2;
        }

        // ---- compute channels 4..7 ----
        #pragma unroll
        for (int c = 0; c < 4; c++) {
            const float xw[WPT + KK - 1] = {
                a0[c].x, a0[c].y, a1[c].x, a1[c].y, a2[c].x,
                a2[c].y, a3[c].x, a3[c].y, a4[c].x, a4[c].y };
            #pragma unroll
            for (int j = 0; j < KK; j++) {
                acc[c + 4][0] = fmaf(xw[j + 0], t[j].x, acc[c + 4][0]);
                acc[c + 4][1] = fmaf(xw[j + 1], t[j].y, acc[c + 4][1]);
            }
        }

        ftap += (size_t)KK * HW;   // next filter row block
        xrow += W_;                // next input row
    }

    // store results
    float* obase = out + (size_t)n * C_ * HW + (size_t)h * W_ + w0;
    #pragma unroll
    for (int c = 0; c < C_; c++) {
        float2 r; r.x = acc[c][0]; r.y = acc[c][1];
        *reinterpret_cast<float2*>(obase + (size_t)c * HW) = r;
    }
}

extern "C" void kernel_launch(void* const* d_in, const int* in_sizes, int n_in,
                              void* d_out, int out_size)
{
    const float* x = (const float*)d_in[0];   // x_in       [2, 8, 256, 512]
    const float* f = (const float*)d_in[1];   // filters    [2, 81, 256, 512]
    const float* b = (const float*)d_in[2];   // biases     [2, 1, 256, 512]
    float* out = (float*)d_out;

    dim3 grid(N_ * H_ * 2);  // 1024 blocks: (n,h) x 2 row-halves
    dim3 block(128);         // 128 threads * WPT(2) = 256 = W/2
    dfl_kernel<<<grid, block>>>(x, f, b, out);
}

// round 13
// speedup vs baseline: 2.3061x; 2.3061x over previous
#include <cuda_runtime.h>
#include <cstddef>

// DynamicFilterLayer: out[n,c,h,w] = sum_{i,j} xpad[n,c,h+i,w+j] * filters[n,i*9+j,h,w] + bias[n,0,h,w]
// N=2, C=8, H=256, W=512, K=9, pad=4.
// R10: exact R7 per-thread structure (WPT=4, float4, front-batched MLP~21, grid-once tap
// stream), but 64-thread blocks each covering HALF a row -> grid 2048 (~1.5x resident
// warps; w-split duplicates zero tap traffic).

#define N_  2
#define C_  8
#define H_  256
#define W_  512
#define KK  9
#define PAD 4
#define WPT 4   // output columns per thread

__global__ void __launch_bounds__(64) dfl_kernel(
    const float* __restrict__ x,      // [N, C, H, W]
    const float* __restrict__ f,      // [N, 81, H, W]
    const float* __restrict__ b,      // [N, 1, H, W]
    float* __restrict__ out)          // [N, C, H, W]
{
    const int row  = blockIdx.x >> 1;                       // (n, h) row id
    const int half = blockIdx.x & 1;                        // which half-row
    const int n    = row >> 8;                              // / H_
    const int h    = row & 255;                             // % H_
    const int w0   = half * (W_ / 2) + threadIdx.x * WPT;   // multiple of 4

    const size_t HW = (size_t)H_ * W_;

    // accumulators initialized with bias
    float acc[C_][WPT];
    {
        const float4 bv = *reinterpret_cast<const float4*>(b + (size_t)n * HW + (size_t)h * W_ + w0);
        #pragma unroll
        for (int c = 0; c < C_; c++) {
            acc[c][0] = bv.x; acc[c][1] = bv.y; acc[c][2] = bv.z; acc[c][3] = bv.w;
        }
    }

    const int i0 = (h < PAD) ? (PAD - h) : 0;
    const int i1 = (h > H_ - 1 - PAD) ? (PAD + H_ - h) : KK;

    // Walking pointers; per-j / per-c offsets are compile-time constants folded into
    // the LDG immediate.
    const float* ftap = f + (size_t)n * (KK * KK) * HW + (size_t)h * W_ + w0 + (size_t)i0 * KK * HW;
    const float* xrow = x + (size_t)n * C_ * HW + (size_t)(h + i0 - PAD) * W_ + w0;

    const bool has_lo = (w0 >= PAD);             // false only for w0==0
    const bool has_hi = (w0 + WPT + PAD <= W_);  // false only for w0==508

    for (int i = i0; i < i1; i++) {
        // ---- batch 1: all 9 tap vectors (MLP 9) ----
        float4 t[KK];
        #pragma unroll
        for (int j = 0; j < KK; j++)
            t[j] = *reinterpret_cast<const float4*>(ftap + (size_t)j * HW);

        // ---- batch 2: x windows for channels 0..3 (12 more loads in flight) ----
        float4 lo[4], md[4], hi[4];
        #pragma unroll
        for (int c = 0; c < 4; c++) {
            const float* xr = xrow + (size_t)c * HW;
            float4 vl = make_float4(0.f, 0.f, 0.f, 0.f);
            float4 vh = make_float4(0.f, 0.f, 0.f, 0.f);
            if (has_lo) vl = *reinterpret_cast<const float4*>(xr - 4);
            md[c] = *reinterpret_cast<const float4*>(xr);
            if (has_hi) vh = *reinterpret_cast<const float4*>(xr + 4);
            lo[c] = vl; hi[c] = vh;
        }

        // ---- compute channels 0..3 ----
        #pragma unroll
        for (int c = 0; c < 4; c++) {
            const float xw[WPT + KK - 1] = {
                lo[c].x, lo[c].y, lo[c].z, lo[c].w,
                md[c].x, md[c].y, md[c].z, md[c].w,
                hi[c].x, hi[c].y, hi[c].z, hi[c].w };
            #pragma unroll
            for (int j = 0; j < KK; j++) {
                const float tj0 = t[j].x, tj1 = t[j].y, tj2 = t[j].z, tj3 = t[j].w;
                acc[c][0] = fmaf(xw[j + 0], tj0, acc[c][0]);
                acc[c][1] = fmaf(xw[j + 1], tj1, acc[c][1]);
                acc[c][2] = fmaf(xw[j + 2], tj2, acc[c][2]);
                acc[c][3] = fmaf(xw[j + 3], tj3, acc[c][3]);
            }
        }

        // ---- batch 3: x windows for channels 4..7 ----
        #pragma unroll
        for (int c = 0; c < 4; c++) {
            const float* xr = xrow + (size_t)(c + 4) * HW;
            float4 vl = make_float4(0.f, 0.f, 0.f, 0.f);
            float4 vh = make_float4(0.f, 0.f, 0.f, 0.f);
            if (has_lo) vl = *reinterpret_cast<const float4*>(xr - 4);
            md[c] = *reinterpret_cast<const float4*>(xr);
            if (has_hi) vh = *reinterpret_cast<const float4*>(xr + 4);
            lo[c] = vl; hi[c] = vh;
        }

        // ---- compute channels 4..7 ----
        #pragma unroll
        for (int c = 0; c < 4; c++) {
            const float xw[WPT + KK - 1] = {
                lo[c].x, lo[c].y, lo[c].z, lo[c].w,
                md[c].x, md[c].y, md[c].z, md[c].w,
                hi[c].x, hi[c].y, hi[c].z, hi[c].w };
            #pragma unroll
            for (int j = 0; j < KK; j++) {
                const float tj0 = t[j].x, tj1 = t[j].y, tj2 = t[j].z, tj3 = t[j].w;
                acc[c + 4][0] = fmaf(xw[j + 0], tj0, acc[c + 4][0]);
                acc[c + 4][1] = fmaf(xw[j + 1], tj1, acc[c + 4][1]);
                acc[c + 4][2] = fmaf(xw[j + 2], tj2, acc[c + 4][2]);
                acc[c + 4][3] = fmaf(xw[j + 3], tj3, acc[c + 4][3]);
            }
        }

        ftap += (size_t)KK * HW;   // next filter row block
        xrow += W_;                // next input row
    }

    // store results
    float* obase = out + (size_t)n * C_ * HW + (size_t)h * W_ + w0;
    #pragma unroll
    for (int c = 0; c < C_; c++) {
        float4 r;
        r.x = acc[c][0]; r.y = acc[c][1]; r.z = acc[c][2]; r.w = acc[c][3];
        *reinterpret_cast<float4*>(obase + (size_t)c * HW) = r;
    }
}

extern "C" void kernel_launch(void* const* d_in, const int* in_sizes, int n_in,
                              void* d_out, int out_size)
{
    const float* x = (const float*)d_in[0];   // x_in       [2, 8, 256, 512]
    const float* f = (const float*)d_in[1];   // filters    [2, 81, 256, 512]
    const float* b = (const float*)d_in[2];   // biases     [2, 1, 256, 512]
    float* out = (float*)d_out;

    dim3 grid(N_ * H_ * 2);  // 2048 blocks: (n,h) x 2 half-rows
    dim3 block(64);          // 64 threads * WPT(4) = 256 = W/2
    dfl_kernel<<<grid, block>>>(x, f, b, out);
}

// round 17
// speedup vs baseline: 2.3481x; 1.0182x over previous
#include <cuda_runtime.h>
#include <cstddef>

// DynamicFilterLayer: out[n,c,h,w] = sum_{i,j} xpad[n,c,h+i,w+j] * filters[n,i*9+j,h,w] + bias[n,0,h,w]
// N=2, C=8, H=256, W=512, K=9, pad=4.
// R13: channel-split INSIDE the block. 64-thread block = 2 warps over the same
// 128-column quarter-row: warp0 -> ch0-3, warp1 -> ch4-7. Duplicated tap loads merge
// in the L1 miss queue (same SM, same cycle window) so DRAM tap traffic stays
// read-once, while total warps double to 4096 (occ ~34%). Per-thread loads keep the
// R7 front-batched float4 shape.

#define N_  2
#define C_  8
#define H_  256
#define W_  512
#define KK  9
#define PAD 4
#define WPT 4   // output columns per thread
#define QW  128 // columns per block (quarter row)

__global__ void __launch_bounds__(64) dfl_kernel(
    const float* __restrict__ x,      // [N, C, H, W]
    const float* __restrict__ f,      // [N, 81, H, W]
    const float* __restrict__ b,      // [N, 1, H, W]
    float* __restrict__ out)          // [N, C, H, W]
{
    const int q   = blockIdx.x & 3;        // quarter of the row
    const int row = blockIdx.x >> 2;       // (n, h) row id
    const int n   = row >> 8;              // / H_
    const int h   = row & 255;             // % H_
    const int c0  = (threadIdx.x >> 5) * 4;                 // warp 0 -> ch0-3, warp 1 -> ch4-7
    const int w0  = q * QW + (threadIdx.x & 31) * WPT;      // multiple of 4

    const size_t HW = (size_t)H_ * W_;

    // accumulators initialized with bias (4 channels per thread)
    float acc[4][WPT];
    {
        const float4 bv = *reinterpret_cast<const float4*>(b + (size_t)n * HW + (size_t)h * W_ + w0);
        #pragma unroll
        for (int c = 0; c < 4; c++) {
            acc[c][0] = bv.x; acc[c][1] = bv.y; acc[c][2] = bv.z; acc[c][3] = bv.w;
        }
    }

    const int i0 = (h < PAD) ? (PAD - h) : 0;
    const int i1 = (h > H_ - 1 - PAD) ? (PAD + H_ - h) : KK;

    // Walking pointers; per-j / per-c offsets are compile-time constants folded into
    // the LDG immediate.
    const float* ftap = f + (size_t)n * (KK * KK) * HW + (size_t)h * W_ + w0 + (size_t)i0 * KK * HW;
    const float* xrow = x + (size_t)(n * C_ + c0) * HW + (size_t)(h + i0 - PAD) * W_ + w0;

    const bool has_lo = (w0 >= PAD);             // false only for w0==0
    const bool has_hi = (w0 + WPT + PAD <= W_);  // false only for w0==508

    for (int i = i0; i < i1; i++) {
        // ---- batch 1: all 9 tap vectors (both warps issue; misses merge in L1) ----
        float4 t[KK];
        #pragma unroll
        for (int j = 0; j < KK; j++)
            t[j] = *reinterpret_cast<const float4*>(ftap + (size_t)j * HW);

        // ---- batch 2: x windows for this warp's channels 0..1 ----
        float4 lo[2], md[2], hi[2];
        #pragma unroll
        for (int c = 0; c < 2; c++) {
            const float* xr = xrow + (size_t)c * HW;
            float4 vl = make_float4(0.f, 0.f, 0.f, 0.f);
            float4 vh = make_float4(0.f, 0.f, 0.f, 0.f);
            if (has_lo) vl = *reinterpret_cast<const float4*>(xr - 4);
            md[c] = *reinterpret_cast<const float4*>(xr);
            if (has_hi) vh = *reinterpret_cast<const float4*>(xr + 4);
            lo[c] = vl; hi[c] = vh;
        }

        // ---- compute channels 0..1 ----
        #pragma unroll
        for (int c = 0; c < 2; c++) {
            const float xw[WPT + KK - 1] = {
                lo[c].x, lo[c].y, lo[c].z, lo[c].w,
                md[c].x, md[c].y, md[c].z, md[c].w,
                hi[c].x, hi[c].y, hi[c].z, hi[c].w };
            #pragma unroll
            for (int j = 0; j < KK; j++) {
                const float tj0 = t[j].x, tj1 = t[j].y, tj2 = t[j].z, tj3 = t[j].w;
                acc[c][0] = fmaf(xw[j + 0], tj0, acc[c][0]);
                acc[c][1] = fmaf(xw[j + 1], tj1, acc[c][1]);
                acc[c][2] = fmaf(xw[j + 2], tj2, acc[c][2]);
                acc[c][3] = fmaf(xw[j + 3], tj3, acc[c][3]);
            }
        }

        // ---- batch 3: x windows for channels 2..3 ----
        #pragma unroll
        for (int c = 0; c < 2; c++) {
            const float* xr = xrow + (size_t)(c + 2) * HW;
            float4 vl = make_float4(0.f, 0.f, 0.f, 0.f);
            float4 vh = make_float4(0.f, 0.f, 0.f, 0.f);
            if (has_lo) vl = *reinterpret_cast<const float4*>(xr - 4);
            md[c] = *reinterpret_cast<const float4*>(xr);
            if (has_hi) vh = *reinterpret_cast<const float4*>(xr + 4);
            lo[c] = vl; hi[c] = vh;
        }

        // ---- compute channels 2..3 ----
        #pragma unroll
        for (int c = 0; c < 2; c++) {
            const float xw[WPT + KK - 1] = {
                lo[c].x, lo[c].y, lo[c].z, lo[c].w,
                md[c].x, md[c].y, md[c].z, md[c].w,
                hi[c].x, hi[c].y, hi[c].z, hi[c].w };
            #pragma unroll
            for (int j = 0; j < KK; j++) {
                const float tj0 = t[j].x, tj1 = t[j].y, tj2 = t[j].z, tj3 = t[j].w;
                acc[c + 2][0] = fmaf(xw[j + 0], tj0, acc[c + 2][0]);
                acc[c + 2][1] = fmaf(xw[j + 1], tj1, acc[c + 2][1]);
                acc[c + 2][2] = fmaf(xw[j + 2], tj2, acc[c + 2][2]);
                acc[c + 2][3] = fmaf(xw[j + 3], tj3, acc[c + 2][3]);
            }
        }

        ftap += (size_t)KK * HW;   // next filter row block
        xrow += W_;                // next input row
    }

    // store results
    float* obase = out + (size_t)(n * C_ + c0) * HW + (size_t)h * W_ + w0;
    #pragma unroll
    for (int c = 0; c < 4; c++) {
        float4 r;
        r.x = acc[c][0]; r.y = acc[c][1]; r.z = acc[c][2]; r.w = acc[c][3];
        *reinterpret_cast<float4*>(obase + (size_t)c * HW) = r;
    }
}

extern "C" void kernel_launch(void* const* d_in, const int* in_sizes, int n_in,
                              void* d_out, int out_size)
{
    const float* x = (const float*)d_in[0];   // x_in       [2, 8, 256, 512]
    const float* f = (const float*)d_in[1];   // filters    [2, 81, 256, 512]
    const float* b = (const float*)d_in[2];   // biases     [2, 1, 256, 512]
    float* out = (float*)d_out;

    dim3 grid(N_ * H_ * 4);  // 2048 blocks: (n,h) x 4 quarter-rows
    dim3 block(64);          // 2 warps: same 128 columns, disjoint channel halves
    dfl_kernel<<<grid, block>>>(x, f, b, out);
}